// round 1
// baseline (speedup 1.0000x reference)
#include <cuda_runtime.h>
#include <cstdint>

#define HH 128
#define NPAD 100096   // >= ceil(100000/64)*64, padded so tile loads/stores never go OOB
#define BM 64
#define BK 32
#define BN 128

// ---------------- scratch (device globals: allocation-free) ----------------
__device__ float g_xp [NPAD * HH];   // projected features per layer
__device__ float g_acc[NPAD * HH];   // aggregation accumulator
__device__ float g_h  [NPAD * HH];   // node embeddings
__device__ float g_inv[NPAD];        // 1/max(deg,1)
__device__ float g_xp0 [NPAD * 2];
__device__ float g_acc0[NPAD * 2];
__device__ float g_cnt [NPAD];

__device__ __forceinline__ float warp_sum(float v) {
#pragma unroll
    for (int o = 16; o > 0; o >>= 1) v += __shfl_xor_sync(0xffffffffu, v, o);
    return v;
}

// ---------------- layer 0: project (2 -> 2) ----------------
__global__ void k_l0(const float* __restrict__ x, const float* __restrict__ Wp,
                     const float* __restrict__ bp, int n) {
    int i = blockIdx.x * blockDim.x + threadIdx.x;
    if (i >= n) return;
    float x0 = x[2 * i], x1 = x[2 * i + 1];
    float a = fmaxf(fmaf(x0, Wp[0], fmaf(x1, Wp[2], bp[0])), 0.f);
    float b = fmaxf(fmaf(x0, Wp[1], fmaf(x1, Wp[3], bp[1])), 0.f);
    g_xp0[2 * i] = a;
    g_xp0[2 * i + 1] = b;
}

// ---------------- layer 0 aggregation + degree count ----------------
__global__ void k_agg0(const int* __restrict__ ei, int E) {
    int e = blockIdx.x * blockDim.x + threadIdx.x;
    if (e >= E) return;
    int s = ei[e], d = ei[E + e];
    float2 v = *(const float2*)&g_xp0[2 * s];
    asm volatile("red.global.add.v2.f32 [%0], {%1, %2};"
                 :: "l"(&g_acc0[2 * d]), "f"(v.x), "f"(v.y) : "memory");
    atomicAdd(&g_cnt[d], 1.0f);
}

// ---------------- layer 0 combine + LN (block per node) ----------------
__global__ void __launch_bounds__(128) k_combine0(const float* __restrict__ Wl,
        const float* __restrict__ bl, const float* __restrict__ Wr,
        const float* __restrict__ lnw, const float* __restrict__ lnb) {
    __shared__ float redA[4], redB[4];
    int i = blockIdx.x, j = threadIdx.x;
    int w = j >> 5, lane = j & 31;
    float invc = 1.0f / fmaxf(g_cnt[i], 1.0f);
    if (j == 0) g_inv[i] = invc;
    float m0 = g_acc0[2 * i] * invc, m1 = g_acc0[2 * i + 1] * invc;
    float p0 = g_xp0[2 * i], p1 = g_xp0[2 * i + 1];
    float v = fmaf(m0, Wl[j], fmaf(m1, Wl[HH + j],
              fmaf(p0, Wr[j], fmaf(p1, Wr[HH + j], bl[j]))));
    float s = warp_sum(v);
    if (lane == 0) redA[w] = s;
    __syncthreads();
    float mu = (redA[0] + redA[1] + redA[2] + redA[3]) * (1.f / HH);
    float d = v - mu;
    float sq = warp_sum(d * d);
    if (lane == 0) redB[w] = sq;
    __syncthreads();
    float var = (redB[0] + redB[1] + redB[2] + redB[3]) * (1.f / HH);
    g_h[(size_t)i * HH + j] = d * rsqrtf(var + 1e-5f) * lnw[j] + lnb[j];
}

// ---------------- proj GEMM: xp = relu(h @ Wp + bp); also zeroes acc ----------------
__global__ void __launch_bounds__(128) k_proj(const float* __restrict__ W,
                                              const float* __restrict__ bias) {
    __shared__ float As[BK][BM + 1];
    __shared__ float Ws[BK][BN];
    const int t = threadIdx.x;
    const int tr = t >> 4, tc = t & 15;
    const int row0 = blockIdx.x * BM;
    const int lr = t >> 1, lcs = (t & 1) * 16;
    const int wr = t >> 2, wcs = (t & 3) * 32;

    float acc[8][8];
#pragma unroll
    for (int i = 0; i < 8; i++)
#pragma unroll
        for (int j = 0; j < 8; j++) acc[i][j] = 0.f;

    for (int k0 = 0; k0 < HH; k0 += BK) {
        __syncthreads();
        const float4* ap = (const float4*)&g_h[(size_t)(row0 + lr) * HH + k0 + lcs];
#pragma unroll
        for (int u = 0; u < 4; u++) {
            float4 v = ap[u];
            As[lcs + u * 4 + 0][lr] = v.x; As[lcs + u * 4 + 1][lr] = v.y;
            As[lcs + u * 4 + 2][lr] = v.z; As[lcs + u * 4 + 3][lr] = v.w;
        }
        const float4* wp = (const float4*)&W[(size_t)(k0 + wr) * HH + wcs];
        float4* wsp = (float4*)&Ws[wr][wcs];
#pragma unroll
        for (int u = 0; u < 8; u++) wsp[u] = wp[u];
        __syncthreads();
#pragma unroll
        for (int kk = 0; kk < BK; kk++) {
            float a[8], w[8];
#pragma unroll
            for (int i = 0; i < 8; i++) a[i] = As[kk][tr * 8 + i];
            float4 w0 = *(const float4*)&Ws[kk][tc * 8];
            float4 w1 = *(const float4*)&Ws[kk][tc * 8 + 4];
            w[0] = w0.x; w[1] = w0.y; w[2] = w0.z; w[3] = w0.w;
            w[4] = w1.x; w[5] = w1.y; w[6] = w1.z; w[7] = w1.w;
#pragma unroll
            for (int i = 0; i < 8; i++)
#pragma unroll
                for (int j = 0; j < 8; j++) acc[i][j] = fmaf(a[i], w[j], acc[i][j]);
        }
    }
    float b[8];
#pragma unroll
    for (int j = 0; j < 8; j++) b[j] = bias[tc * 8 + j];
    const float4 z = make_float4(0.f, 0.f, 0.f, 0.f);
#pragma unroll
    for (int i = 0; i < 8; i++) {
        size_t base = (size_t)(row0 + tr * 8 + i) * HH + tc * 8;
        float4 o0, o1;
        o0.x = fmaxf(acc[i][0] + b[0], 0.f); o0.y = fmaxf(acc[i][1] + b[1], 0.f);
        o0.z = fmaxf(acc[i][2] + b[2], 0.f); o0.w = fmaxf(acc[i][3] + b[3], 0.f);
        o1.x = fmaxf(acc[i][4] + b[4], 0.f); o1.y = fmaxf(acc[i][5] + b[5], 0.f);
        o1.z = fmaxf(acc[i][6] + b[6], 0.f); o1.w = fmaxf(acc[i][7] + b[7], 0.f);
        *(float4*)&g_xp[base] = o0;
        *(float4*)&g_xp[base + 4] = o1;
        *(float4*)&g_acc[base] = z;
        *(float4*)&g_acc[base + 4] = z;
    }
}

// ---------------- heavy aggregation: warp per edge, f32x4 reductions ----------------
__global__ void __launch_bounds__(256) k_agg(const int* __restrict__ ei, int E) {
    int gw = (blockIdx.x * 256 + threadIdx.x) >> 5;
    int lane = threadIdx.x & 31;
    if (gw >= E) return;
    int s = ei[gw], d = ei[E + gw];
    float4 v = *(const float4*)&g_xp[(size_t)s * HH + lane * 4];
    float* p = &g_acc[(size_t)d * HH + lane * 4];
    asm volatile("red.global.add.v4.f32 [%0], {%1, %2, %3, %4};"
                 :: "l"(p), "f"(v.x), "f"(v.y), "f"(v.z), "f"(v.w) : "memory");
}

// ---------------- combine GEMM (K=256, row-scaled first half) + LN ----------------
__global__ void __launch_bounds__(128) k_combine(const float* __restrict__ Wl,
        const float* __restrict__ Wr, const float* __restrict__ bl,
        const float* __restrict__ lnw, const float* __restrict__ lnb) {
    __shared__ __align__(16) float pool[BM * BN];  // 32KB, unioned
    float (*As)[BM + 1] = (float(*)[BM + 1])pool;            // 2080 floats
    float (*Ws)[BN]     = (float(*)[BN])(pool + 2080);       // 4096 floats
    const int t = threadIdx.x;
    const int tr = t >> 4, tc = t & 15;
    const int row0 = blockIdx.x * BM;
    const int lr = t >> 1, lcs = (t & 1) * 16;
    const int wr = t >> 2, wcs = (t & 3) * 32;
    const float invr = g_inv[row0 + lr];

    float acc[8][8];
#pragma unroll
    for (int i = 0; i < 8; i++)
#pragma unroll
        for (int j = 0; j < 8; j++) acc[i][j] = 0.f;

    for (int k0 = 0; k0 < 2 * HH; k0 += BK) {
        __syncthreads();
        if (k0 < HH) {
            const float4* ap = (const float4*)&g_acc[(size_t)(row0 + lr) * HH + k0 + lcs];
#pragma unroll
            for (int u = 0; u < 4; u++) {
                float4 v = ap[u];
                As[lcs + u * 4 + 0][lr] = v.x * invr; As[lcs + u * 4 + 1][lr] = v.y * invr;
                As[lcs + u * 4 + 2][lr] = v.z * invr; As[lcs + u * 4 + 3][lr] = v.w * invr;
            }
            const float4* wp = (const float4*)&Wl[(size_t)(k0 + wr) * HH + wcs];
            float4* wsp = (float4*)&Ws[wr][wcs];
#pragma unroll
            for (int u = 0; u < 8; u++) wsp[u] = wp[u];
        } else {
            const float4* ap = (const float4*)&g_xp[(size_t)(row0 + lr) * HH + (k0 - HH) + lcs];
#pragma unroll
            for (int u = 0; u < 4; u++) {
                float4 v = ap[u];
                As[lcs + u * 4 + 0][lr] = v.x; As[lcs + u * 4 + 1][lr] = v.y;
                As[lcs + u * 4 + 2][lr] = v.z; As[lcs + u * 4 + 3][lr] = v.w;
            }
            const float4* wp = (const float4*)&Wr[(size_t)(k0 - HH + wr) * HH + wcs];
            float4* wsp = (float4*)&Ws[wr][wcs];
#pragma unroll
            for (int u = 0; u < 8; u++) wsp[u] = wp[u];
        }
        __syncthreads();
#pragma unroll
        for (int kk = 0; kk < BK; kk++) {
            float a[8], w[8];
#pragma unroll
            for (int i = 0; i < 8; i++) a[i] = As[kk][tr * 8 + i];
            float4 w0 = *(const float4*)&Ws[kk][tc * 8];
            float4 w1 = *(const float4*)&Ws[kk][tc * 8 + 4];
            w[0] = w0.x; w[1] = w0.y; w[2] = w0.z; w[3] = w0.w;
            w[4] = w1.x; w[5] = w1.y; w[6] = w1.z; w[7] = w1.w;
#pragma unroll
            for (int i = 0; i < 8; i++)
#pragma unroll
                for (int j = 0; j < 8; j++) acc[i][j] = fmaf(a[i], w[j], acc[i][j]);
        }
    }
    float b[8];
#pragma unroll
    for (int j = 0; j < 8; j++) b[j] = bl[tc * 8 + j];
    __syncthreads();   // done with As/Ws — reuse pool as C tile
#pragma unroll
    for (int i = 0; i < 8; i++)
#pragma unroll
        for (int j = 0; j < 8; j++)
            pool[(tr * 8 + i) * BN + tc * 8 + j] = acc[i][j] + b[j];
    __syncthreads();

    // per-row LayerNorm: 4 warps x 16 rows
    int w = t >> 5, lane = t & 31;
    float lw[4], lb[4];
#pragma unroll
    for (int s = 0; s < 4; s++) { lw[s] = lnw[lane + 32 * s]; lb[s] = lnb[lane + 32 * s]; }
    for (int r = w; r < BM; r += 4) {
        float v[4], su = 0.f;
#pragma unroll
        for (int s = 0; s < 4; s++) { v[s] = pool[r * BN + lane + 32 * s]; su += v[s]; }
        su = warp_sum(su);
        float mu = su * (1.f / HH);
        float vs = 0.f;
#pragma unroll
        for (int s = 0; s < 4; s++) { float d = v[s] - mu; vs += d * d; }
        vs = warp_sum(vs);
        float rstd = rsqrtf(vs * (1.f / HH) + 1e-5f);
        size_t base = (size_t)(row0 + r) * HH;
#pragma unroll
        for (int s = 0; s < 4; s++)
            g_h[base + lane + 32 * s] = (v[s] - mu) * rstd * lw[s] + lb[s];
    }
}

// ---------------- edge MLP: gather-GEMM (K=256) + fused W2 reduction ----------------
__global__ void __launch_bounds__(128) k_edgemlp(const int* __restrict__ eli, int Q,
        const float* __restrict__ W1, const float* __restrict__ b1,
        const float* __restrict__ W2, const float* __restrict__ b2,
        float* __restrict__ out) {
    __shared__ __align__(16) float pool[BM * BN];
    __shared__ int sbase[BM], dbase[BM];
    __shared__ float W2s[BN];
    float (*As)[BM + 1] = (float(*)[BM + 1])pool;
    float (*Ws)[BN]     = (float(*)[BN])(pool + 2080);
    const int t = threadIdx.x;
    const int tr = t >> 4, tc = t & 15;
    const int q0 = blockIdx.x * BM;
    const int lr = t >> 1, lcs = (t & 1) * 16;
    const int wr = t >> 2, wcs = (t & 3) * 32;

    if (t < BM) {
        int q = q0 + t, s = 0, d = 0;
        if (q < Q) { s = eli[q]; d = eli[Q + q]; }
        sbase[t] = s * HH; dbase[t] = d * HH;
    }
    W2s[t] = W2[t];
    __syncthreads();
    const int sb = sbase[lr], db = dbase[lr];

    float acc[8][8];
#pragma unroll
    for (int i = 0; i < 8; i++)
#pragma unroll
        for (int j = 0; j < 8; j++) acc[i][j] = 0.f;

    for (int k0 = 0; k0 < 2 * HH; k0 += BK) {
        __syncthreads();
        const float4* ap = (k0 < HH)
            ? (const float4*)&g_h[(size_t)sb + k0 + lcs]
            : (const float4*)&g_h[(size_t)db + (k0 - HH) + lcs];
#pragma unroll
        for (int u = 0; u < 4; u++) {
            float4 v = ap[u];
            As[lcs + u * 4 + 0][lr] = v.x; As[lcs + u * 4 + 1][lr] = v.y;
            As[lcs + u * 4 + 2][lr] = v.z; As[lcs + u * 4 + 3][lr] = v.w;
        }
        const float4* wp = (const float4*)&W1[(size_t)(k0 + wr) * HH + wcs];
        float4* wsp = (float4*)&Ws[wr][wcs];
#pragma unroll
        for (int u = 0; u < 8; u++) wsp[u] = wp[u];
        __syncthreads();
#pragma unroll
        for (int kk = 0; kk < BK; kk++) {
            float a[8], w[8];
#pragma unroll
            for (int i = 0; i < 8; i++) a[i] = As[kk][tr * 8 + i];
            float4 w0 = *(const float4*)&Ws[kk][tc * 8];
            float4 w1 = *(const float4*)&Ws[kk][tc * 8 + 4];
            w[0] = w0.x; w[1] = w0.y; w[2] = w0.z; w[3] = w0.w;
            w[4] = w1.x; w[5] = w1.y; w[6] = w1.z; w[7] = w1.w;
#pragma unroll
            for (int i = 0; i < 8; i++)
#pragma unroll
                for (int j = 0; j < 8; j++) acc[i][j] = fmaf(a[i], w[j], acc[i][j]);
        }
    }
    float b[8];
#pragma unroll
    for (int j = 0; j < 8; j++) b[j] = b1[tc * 8 + j];
    __syncthreads();
#pragma unroll
    for (int i = 0; i < 8; i++)
#pragma unroll
        for (int j = 0; j < 8; j++)
            pool[(tr * 8 + i) * BN + tc * 8 + j] = fmaxf(acc[i][j] + b[j], 0.f);
    __syncthreads();

    int w = t >> 5, lane = t & 31;
    float b2v = b2[0];
    for (int r = w; r < BM; r += 4) {
        float su = 0.f;
#pragma unroll
        for (int s = 0; s < 4; s++)
            su = fmaf(pool[r * BN + lane + 32 * s], W2s[lane + 32 * s], su);
        su = warp_sum(su);
        int q = q0 + r;
        if (lane == 0 && q < Q) out[q] = su + b2v;
    }
}

// ---------------- host launch ----------------
extern "C" void kernel_launch(void* const* d_in, const int* in_sizes, int n_in,
                              void* d_out, int out_size) {
    const float* x    = (const float*)d_in[0];
    const int*   ei   = (const int*)d_in[1];
    const int*   eli  = (const int*)d_in[2];
    const float* p0Wp = (const float*)d_in[3];
    const float* p0bp = (const float*)d_in[4];
    const float* p0Wl = (const float*)d_in[5];
    const float* p0bl = (const float*)d_in[6];
    const float* p0Wr = (const float*)d_in[7];
    const float* Wp_s = (const float*)d_in[8];
    const float* bp_s = (const float*)d_in[9];
    const float* Wl_s = (const float*)d_in[10];
    const float* bl_s = (const float*)d_in[11];
    const float* Wr_s = (const float*)d_in[12];
    const float* ln_w = (const float*)d_in[13];
    const float* ln_b = (const float*)d_in[14];
    const float* eW1  = (const float*)d_in[15];
    const float* eb1  = (const float*)d_in[16];
    const float* eW2  = (const float*)d_in[17];
    const float* eb2  = (const float*)d_in[18];
    float* out = (float*)d_out;

    const int n = in_sizes[0] / 2;
    const int E = in_sizes[1] / 2;
    const int Q = in_sizes[2] / 2;

    void *acc0p = nullptr, *cntp = nullptr;
    cudaGetSymbolAddress(&acc0p, g_acc0);
    cudaGetSymbolAddress(&cntp, g_cnt);
    cudaMemsetAsync(acc0p, 0, (size_t)n * 2 * sizeof(float));
    cudaMemsetAsync(cntp, 0, (size_t)n * sizeof(float));

    k_l0<<<(n + 255) / 256, 256>>>(x, p0Wp, p0bp, n);
    k_agg0<<<(E + 255) / 256, 256>>>(ei, E);
    k_combine0<<<n, 128>>>(p0Wl, p0bl, p0Wr, ln_w, ln_b);

    const int gb = (n + BM - 1) / BM;
    const long long aggThreads = (long long)E * 32;
    const int aggBlocks = (int)((aggThreads + 255) / 256);
    for (int l = 0; l < 2; l++) {
        k_proj<<<gb, 128>>>(Wp_s + (size_t)l * HH * HH, bp_s + (size_t)l * HH);
        k_agg<<<aggBlocks, 256>>>(ei, E);
        k_combine<<<gb, 128>>>(Wl_s + (size_t)l * HH * HH, Wr_s + (size_t)l * HH * HH,
                               bl_s + (size_t)l * HH,
                               ln_w + (size_t)(l + 1) * HH, ln_b + (size_t)(l + 1) * HH);
    }
    k_edgemlp<<<(Q + BM - 1) / BM, 128>>>(eli, Q, eW1, eb1, eW2, eb2, out);
}

// round 2
// speedup vs baseline: 1.0355x; 1.0355x over previous
#include <cuda_runtime.h>
#include <cstdint>

#define HH 128
#define NPAD 100096   // ceil(100000/128)*128
#define BM 128
#define BN 128
#define BK 16
#define NTHREADS 256

// ---------------- scratch (device globals: allocation-free) ----------------
__device__ float g_xp [NPAD * HH];
__device__ float g_acc[NPAD * HH];
__device__ float g_h  [NPAD * HH];
__device__ float g_inv[NPAD];
__device__ float g_xp0 [NPAD * 2];
__device__ float g_acc0[NPAD * 2];
__device__ float g_cnt [NPAD];

__device__ __forceinline__ float warp_sum(float v) {
#pragma unroll
    for (int o = 16; o > 0; o >>= 1) v += __shfl_xor_sync(0xffffffffu, v, o);
    return v;
}
// reduce across the 16-thread group sharing a C-row (contiguous lanes)
__device__ __forceinline__ float hw_sum(float v) {
    v += __shfl_xor_sync(0xffffffffu, v, 8);
    v += __shfl_xor_sync(0xffffffffu, v, 4);
    v += __shfl_xor_sync(0xffffffffu, v, 2);
    v += __shfl_xor_sync(0xffffffffu, v, 1);
    return v;
}

// ---------------- layer 0: project (2 -> 2) ----------------
__global__ void k_l0(const float* __restrict__ x, const float* __restrict__ Wp,
                     const float* __restrict__ bp, int n) {
    int i = blockIdx.x * blockDim.x + threadIdx.x;
    if (i >= n) return;
    float x0 = x[2 * i], x1 = x[2 * i + 1];
    float a = fmaxf(fmaf(x0, Wp[0], fmaf(x1, Wp[2], bp[0])), 0.f);
    float b = fmaxf(fmaf(x0, Wp[1], fmaf(x1, Wp[3], bp[1])), 0.f);
    g_xp0[2 * i] = a;
    g_xp0[2 * i + 1] = b;
}

// ---------------- layer 0 aggregation + degree count ----------------
__global__ void k_agg0(const int* __restrict__ ei, int E) {
    int e = blockIdx.x * blockDim.x + threadIdx.x;
    if (e >= E) return;
    int s = ei[e], d = ei[E + e];
    float2 v = *(const float2*)&g_xp0[2 * s];
    asm volatile("red.global.add.v2.f32 [%0], {%1, %2};"
                 :: "l"(&g_acc0[2 * d]), "f"(v.x), "f"(v.y) : "memory");
    atomicAdd(&g_cnt[d], 1.0f);
}

// ---------------- layer 0 combine + LN (block per node) ----------------
__global__ void __launch_bounds__(128) k_combine0(const float* __restrict__ Wl,
        const float* __restrict__ bl, const float* __restrict__ Wr,
        const float* __restrict__ lnw, const float* __restrict__ lnb) {
    __shared__ float redA[4], redB[4];
    int i = blockIdx.x, j = threadIdx.x;
    int w = j >> 5, lane = j & 31;
    float invc = 1.0f / fmaxf(g_cnt[i], 1.0f);
    if (j == 0) g_inv[i] = invc;
    float m0 = g_acc0[2 * i] * invc, m1 = g_acc0[2 * i + 1] * invc;
    float p0 = g_xp0[2 * i], p1 = g_xp0[2 * i + 1];
    float v = fmaf(m0, Wl[j], fmaf(m1, Wl[HH + j],
              fmaf(p0, Wr[j], fmaf(p1, Wr[HH + j], bl[j]))));
    float s = warp_sum(v);
    if (lane == 0) redA[w] = s;
    __syncthreads();
    float mu = (redA[0] + redA[1] + redA[2] + redA[3]) * (1.f / HH);
    float d = v - mu;
    float sq = warp_sum(d * d);
    if (lane == 0) redB[w] = sq;
    __syncthreads();
    float var = (redB[0] + redB[1] + redB[2] + redB[3]) * (1.f / HH);
    g_h[(size_t)i * HH + j] = d * rsqrtf(var + 1e-5f) * lnw[j] + lnb[j];
}

// =================== shared GEMM-core helpers ===================
// Tile: BM=128 x BN=128, BK=16, 256 threads, 8x8 per-thread, double-buffered.
// A-load: thread t -> row ar=t>>1, col-offset ac=(t&1)*8 (two float4s).
// W-load: thread t -> rows wrow=t>>5 and wrow+8, col wcol=(t&31)*4 (float4s).

#define GEMM_COMPUTE(cur)                                                     \
    _Pragma("unroll")                                                         \
    for (int kk = 0; kk < BK; kk++) {                                         \
        float4 a0 = *(const float4*)&As[cur][kk][tr * 8];                     \
        float4 a1 = *(const float4*)&As[cur][kk][tr * 8 + 4];                 \
        float4 w0 = *(const float4*)&Ws[cur][kk][tc * 8];                     \
        float4 w1 = *(const float4*)&Ws[cur][kk][tc * 8 + 4];                 \
        float a[8] = {a0.x, a0.y, a0.z, a0.w, a1.x, a1.y, a1.z, a1.w};        \
        float w[8] = {w0.x, w0.y, w0.z, w0.w, w1.x, w1.y, w1.z, w1.w};        \
        _Pragma("unroll")                                                     \
        for (int i = 0; i < 8; i++)                                           \
            _Pragma("unroll")                                                 \
            for (int j = 0; j < 8; j++)                                       \
                acc[i][j] = fmaf(a[i], w[j], acc[i][j]);                      \
    }

#define STORE_TILES(buf, sc)                                                  \
    {                                                                         \
        As[buf][ac + 0][ar] = pa0.x * sc; As[buf][ac + 1][ar] = pa0.y * sc;   \
        As[buf][ac + 2][ar] = pa0.z * sc; As[buf][ac + 3][ar] = pa0.w * sc;   \
        As[buf][ac + 4][ar] = pa1.x * sc; As[buf][ac + 5][ar] = pa1.y * sc;   \
        As[buf][ac + 6][ar] = pa1.z * sc; As[buf][ac + 7][ar] = pa1.w * sc;   \
        *(float4*)&Ws[buf][wrow][wcol] = pw0;                                 \
        *(float4*)&Ws[buf][wrow + 8][wcol] = pw1;                             \
    }

// ---------------- proj GEMM: xp = relu(h @ Wp + bp); also zeroes acc ----------------
__global__ void __launch_bounds__(NTHREADS) k_proj(const float* __restrict__ W,
                                                   const float* __restrict__ bias) {
    __shared__ float As[2][BK][BM + 4];
    __shared__ float Ws[2][BK][BN];
    const int t = threadIdx.x;
    const int tr = t >> 4, tc = t & 15;
    const int row0 = blockIdx.x * BM;
    const int ar = t >> 1, ac = (t & 1) * 8;
    const int wrow = t >> 5, wcol = (t & 31) * 4;
    const float* Abase = &g_h[(size_t)(row0 + ar) * HH];

    float4 pa0, pa1, pw0, pw1;
    pa0 = *(const float4*)(Abase + ac);
    pa1 = *(const float4*)(Abase + ac + 4);
    pw0 = *(const float4*)&W[(size_t)wrow * HH + wcol];
    pw1 = *(const float4*)&W[(size_t)(wrow + 8) * HH + wcol];
    STORE_TILES(0, 1.0f);
    __syncthreads();

    float acc[8][8];
#pragma unroll
    for (int i = 0; i < 8; i++)
#pragma unroll
        for (int j = 0; j < 8; j++) acc[i][j] = 0.f;

    const int NT = HH / BK;  // 8
#pragma unroll
    for (int it = 0; it < NT; it++) {
        int cur = it & 1;
        if (it + 1 < NT) {
            int k0 = (it + 1) * BK;
            pa0 = *(const float4*)(Abase + k0 + ac);
            pa1 = *(const float4*)(Abase + k0 + ac + 4);
            pw0 = *(const float4*)&W[(size_t)(k0 + wrow) * HH + wcol];
            pw1 = *(const float4*)&W[(size_t)(k0 + wrow + 8) * HH + wcol];
        }
        GEMM_COMPUTE(cur)
        if (it + 1 < NT) STORE_TILES(cur ^ 1, 1.0f);
        __syncthreads();
    }

    float b[8];
#pragma unroll
    for (int j = 0; j < 8; j++) b[j] = bias[tc * 8 + j];
    const float4 z = make_float4(0.f, 0.f, 0.f, 0.f);
#pragma unroll
    for (int i = 0; i < 8; i++) {
        size_t base = (size_t)(row0 + tr * 8 + i) * HH + tc * 8;
        float4 o0, o1;
        o0.x = fmaxf(acc[i][0] + b[0], 0.f); o0.y = fmaxf(acc[i][1] + b[1], 0.f);
        o0.z = fmaxf(acc[i][2] + b[2], 0.f); o0.w = fmaxf(acc[i][3] + b[3], 0.f);
        o1.x = fmaxf(acc[i][4] + b[4], 0.f); o1.y = fmaxf(acc[i][5] + b[5], 0.f);
        o1.z = fmaxf(acc[i][6] + b[6], 0.f); o1.w = fmaxf(acc[i][7] + b[7], 0.f);
        *(float4*)&g_xp[base] = o0;
        *(float4*)&g_xp[base + 4] = o1;
        *(float4*)&g_acc[base] = z;
        *(float4*)&g_acc[base + 4] = z;
    }
}

// ---------------- heavy aggregation: warp per edge, f32x4 reductions ----------------
__global__ void __launch_bounds__(256) k_agg(const int* __restrict__ ei, int E) {
    int gw = (blockIdx.x * 256 + threadIdx.x) >> 5;
    int lane = threadIdx.x & 31;
    if (gw >= E) return;
    int s = ei[gw], d = ei[E + gw];
    float4 v = *(const float4*)&g_xp[(size_t)s * HH + lane * 4];
    float* p = &g_acc[(size_t)d * HH + lane * 4];
    asm volatile("red.global.add.v4.f32 [%0], {%1, %2, %3, %4};"
                 :: "l"(p), "f"(v.x), "f"(v.y), "f"(v.z), "f"(v.w) : "memory");
}

// ---------------- combine GEMM (K=256: mean-scaled acc | xp) + fused LN ----------------
__global__ void __launch_bounds__(NTHREADS) k_combine(const float* __restrict__ Wl,
        const float* __restrict__ Wr, const float* __restrict__ bl,
        const float* __restrict__ lnw, const float* __restrict__ lnb) {
    __shared__ float As[2][BK][BM + 4];
    __shared__ float Ws[2][BK][BN];
    const int t = threadIdx.x;
    const int tr = t >> 4, tc = t & 15;
    const int row0 = blockIdx.x * BM;
    const int ar = t >> 1, ac = (t & 1) * 8;
    const int wrow = t >> 5, wcol = (t & 31) * 4;
    const float invr = g_inv[row0 + ar];
    const float* Aa = &g_acc[(size_t)(row0 + ar) * HH];
    const float* Ax = &g_xp[(size_t)(row0 + ar) * HH];

    float4 pa0, pa1, pw0, pw1;
    pa0 = *(const float4*)(Aa + ac);
    pa1 = *(const float4*)(Aa + ac + 4);
    pw0 = *(const float4*)&Wl[(size_t)wrow * HH + wcol];
    pw1 = *(const float4*)&Wl[(size_t)(wrow + 8) * HH + wcol];
    STORE_TILES(0, invr);
    __syncthreads();

    float acc[8][8];
#pragma unroll
    for (int i = 0; i < 8; i++)
#pragma unroll
        for (int j = 0; j < 8; j++) acc[i][j] = 0.f;

    const int NT = 2 * HH / BK;  // 16
    float nsc = invr;
#pragma unroll
    for (int it = 0; it < NT; it++) {
        int cur = it & 1;
        if (it + 1 < NT) {
            int nx = it + 1;
            const float* Ap; const float* Wp_;
            if (nx < 8) { Ap = Aa + nx * BK; Wp_ = Wl + (size_t)nx * BK * HH; nsc = invr; }
            else        { Ap = Ax + (nx - 8) * BK; Wp_ = Wr + (size_t)(nx - 8) * BK * HH; nsc = 1.0f; }
            pa0 = *(const float4*)(Ap + ac);
            pa1 = *(const float4*)(Ap + ac + 4);
            pw0 = *(const float4*)&Wp_[(size_t)wrow * HH + wcol];
            pw1 = *(const float4*)&Wp_[(size_t)(wrow + 8) * HH + wcol];
        }
        GEMM_COMPUTE(cur)
        if (it + 1 < NT) STORE_TILES(cur ^ 1, nsc);
        __syncthreads();
    }

    float b[8], lw[8], lb2[8];
#pragma unroll
    for (int j = 0; j < 8; j++) {
        b[j] = bl[tc * 8 + j]; lw[j] = lnw[tc * 8 + j]; lb2[j] = lnb[tc * 8 + j];
    }
#pragma unroll
    for (int i = 0; i < 8; i++) {
        float v[8]; float s = 0.f;
#pragma unroll
        for (int j = 0; j < 8; j++) { v[j] = acc[i][j] + b[j]; s += v[j]; }
        s = hw_sum(s);
        float mu = s * (1.f / HH);
        float q = 0.f;
#pragma unroll
        for (int j = 0; j < 8; j++) { v[j] -= mu; q += v[j] * v[j]; }
        q = hw_sum(q);
        float rstd = rsqrtf(q * (1.f / HH) + 1e-5f);
        float4 o0, o1;
        o0.x = v[0] * rstd * lw[0] + lb2[0]; o0.y = v[1] * rstd * lw[1] + lb2[1];
        o0.z = v[2] * rstd * lw[2] + lb2[2]; o0.w = v[3] * rstd * lw[3] + lb2[3];
        o1.x = v[4] * rstd * lw[4] + lb2[4]; o1.y = v[5] * rstd * lw[5] + lb2[5];
        o1.z = v[6] * rstd * lw[6] + lb2[6]; o1.w = v[7] * rstd * lw[7] + lb2[7];
        size_t base = (size_t)(row0 + tr * 8 + i) * HH + tc * 8;
        *(float4*)&g_h[base] = o0;
        *(float4*)&g_h[base + 4] = o1;
    }
}

// ---------------- edge MLP: gather-GEMM (K=256) + fused W2 reduction ----------------
__global__ void __launch_bounds__(NTHREADS) k_edgemlp(const int* __restrict__ eli, int Q,
        const float* __restrict__ W1, const float* __restrict__ b1,
        const float* __restrict__ W2, const float* __restrict__ b2,
        float* __restrict__ out) {
    __shared__ float As[2][BK][BM + 4];
    __shared__ float Ws[2][BK][BN];
    __shared__ int sbase[BM], dbase[BM];
    const int t = threadIdx.x;
    const int tr = t >> 4, tc = t & 15;
    const int q0 = blockIdx.x * BM;
    const int ar = t >> 1, ac = (t & 1) * 8;
    const int wrow = t >> 5, wcol = (t & 31) * 4;

    if (t < BM) {
        int q = q0 + t, s = 0, d = 0;
        if (q < Q) { s = eli[q]; d = eli[Q + q]; }
        sbase[t] = s * HH; dbase[t] = d * HH;
    }
    __syncthreads();
    const float* Asrc = &g_h[(size_t)sbase[ar]];
    const float* Adst = &g_h[(size_t)dbase[ar]];

    float4 pa0, pa1, pw0, pw1;
    pa0 = *(const float4*)(Asrc + ac);
    pa1 = *(const float4*)(Asrc + ac + 4);
    pw0 = *(const float4*)&W1[(size_t)wrow * HH + wcol];
    pw1 = *(const float4*)&W1[(size_t)(wrow + 8) * HH + wcol];
    STORE_TILES(0, 1.0f);
    __syncthreads();

    float acc[8][8];
#pragma unroll
    for (int i = 0; i < 8; i++)
#pragma unroll
        for (int j = 0; j < 8; j++) acc[i][j] = 0.f;

    const int NT = 2 * HH / BK;  // 16
#pragma unroll
    for (int it = 0; it < NT; it++) {
        int cur = it & 1;
        if (it + 1 < NT) {
            int nx = it + 1;
            const float* Ap = (nx < 8) ? (Asrc + nx * BK) : (Adst + (nx - 8) * BK);
            const float* Wp_ = W1 + (size_t)nx * BK * HH;
            pa0 = *(const float4*)(Ap + ac);
            pa1 = *(const float4*)(Ap + ac + 4);
            pw0 = *(const float4*)&Wp_[(size_t)wrow * HH + wcol];
            pw1 = *(const float4*)&Wp_[(size_t)(wrow + 8) * HH + wcol];
        }
        GEMM_COMPUTE(cur)
        if (it + 1 < NT) STORE_TILES(cur ^ 1, 1.0f);
        __syncthreads();
    }

    float b[8], w2[8];
#pragma unroll
    for (int j = 0; j < 8; j++) { b[j] = b1[tc * 8 + j]; w2[j] = W2[tc * 8 + j]; }
    float b2v = b2[0];
#pragma unroll
    for (int i = 0; i < 8; i++) {
        float s = 0.f;
#pragma unroll
        for (int j = 0; j < 8; j++)
            s = fmaf(fmaxf(acc[i][j] + b[j], 0.f), w2[j], s);
        s = hw_sum(s);
        int q = q0 + tr * 8 + i;
        if (tc == 0 && q < Q) out[q] = s + b2v;
    }
}

// ---------------- host launch ----------------
extern "C" void kernel_launch(void* const* d_in, const int* in_sizes, int n_in,
                              void* d_out, int out_size) {
    const float* x    = (const float*)d_in[0];
    const int*   ei   = (const int*)d_in[1];
    const int*   eli  = (const int*)d_in[2];
    const float* p0Wp = (const float*)d_in[3];
    const float* p0bp = (const float*)d_in[4];
    const float* p0Wl = (const float*)d_in[5];
    const float* p0bl = (const float*)d_in[6];
    const float* p0Wr = (const float*)d_in[7];
    const float* Wp_s = (const float*)d_in[8];
    const float* bp_s = (const float*)d_in[9];
    const float* Wl_s = (const float*)d_in[10];
    const float* bl_s = (const float*)d_in[11];
    const float* Wr_s = (const float*)d_in[12];
    const float* ln_w = (const float*)d_in[13];
    const float* ln_b = (const float*)d_in[14];
    const float* eW1  = (const float*)d_in[15];
    const float* eb1  = (const float*)d_in[16];
    const float* eW2  = (const float*)d_in[17];
    const float* eb2  = (const float*)d_in[18];
    float* out = (float*)d_out;

    const int n = in_sizes[0] / 2;
    const int E = in_sizes[1] / 2;
    const int Q = in_sizes[2] / 2;

    void *acc0p = nullptr, *cntp = nullptr;
    cudaGetSymbolAddress(&acc0p, g_acc0);
    cudaGetSymbolAddress(&cntp, g_cnt);
    cudaMemsetAsync(acc0p, 0, (size_t)n * 2 * sizeof(float));
    cudaMemsetAsync(cntp, 0, (size_t)n * sizeof(float));

    k_l0<<<(n + 255) / 256, 256>>>(x, p0Wp, p0bp, n);
    k_agg0<<<(E + 255) / 256, 256>>>(ei, E);
    k_combine0<<<n, 128>>>(p0Wl, p0bl, p0Wr, ln_w, ln_b);

    const int gb = (n + BM - 1) / BM;   // 782
    const long long aggThreads = (long long)E * 32;
    const int aggBlocks = (int)((aggThreads + 255) / 256);
    for (int l = 0; l < 2; l++) {
        k_proj<<<gb, NTHREADS>>>(Wp_s + (size_t)l * HH * HH, bp_s + (size_t)l * HH);
        k_agg<<<aggBlocks, 256>>>(ei, E);
        k_combine<<<gb, NTHREADS>>>(Wl_s + (size_t)l * HH * HH, Wr_s + (size_t)l * HH * HH,
                                    bl_s + (size_t)l * HH,
                                    ln_w + (size_t)(l + 1) * HH, ln_b + (size_t)(l + 1) * HH);
    }
    k_edgemlp<<<(Q + BM - 1) / BM, NTHREADS>>>(eli, Q, eW1, eb1, eW2, eb2, out);
}

// round 3
// speedup vs baseline: 1.4269x; 1.3781x over previous
#include <cuda_runtime.h>
#include <cstdint>

#define HH 128
#define NPAD 100096
#define BM 64
#define BN 128
#define BK 16
#define NTH 256

// ---------------- scratch ----------------
__device__ float g_xp [NPAD * HH];
__device__ float g_acc[NPAD * HH];
__device__ float g_h  [NPAD * HH];
__device__ float g_inv[NPAD];
__device__ float g_xp0 [NPAD * 2];
__device__ float g_acc0[NPAD * 2];
__device__ float g_cnt [NPAD];

__device__ __forceinline__ float warp_sum(float v) {
#pragma unroll
    for (int o = 16; o > 0; o >>= 1) v += __shfl_xor_sync(0xffffffffu, v, o);
    return v;
}

__device__ __forceinline__ void cp16(void* dst, const void* src) {
    uint32_t d = (uint32_t)__cvta_generic_to_shared(dst);
    asm volatile("cp.async.ca.shared.global [%0], [%1], 16;" :: "r"(d), "l"(src));
}
#define CP_COMMIT() asm volatile("cp.async.commit_group;")
#define CP_WAIT0()  asm volatile("cp.async.wait_group 0;" ::: "memory")

// ---------------- layer 0: project (2 -> 2) ----------------
__global__ void k_l0(const float* __restrict__ x, const float* __restrict__ Wp,
                     const float* __restrict__ bp, int n) {
    int i = blockIdx.x * blockDim.x + threadIdx.x;
    if (i >= n) return;
    float x0 = x[2 * i], x1 = x[2 * i + 1];
    float a = fmaxf(fmaf(x0, Wp[0], fmaf(x1, Wp[2], bp[0])), 0.f);
    float b = fmaxf(fmaf(x0, Wp[1], fmaf(x1, Wp[3], bp[1])), 0.f);
    g_xp0[2 * i] = a;
    g_xp0[2 * i + 1] = b;
}

// ---------------- layer 0 aggregation + degree count ----------------
__global__ void k_agg0(const int* __restrict__ ei, int E) {
    int e = blockIdx.x * blockDim.x + threadIdx.x;
    if (e >= E) return;
    int s = ei[e], d = ei[E + e];
    float2 v = *(const float2*)&g_xp0[2 * s];
    asm volatile("red.global.add.v2.f32 [%0], {%1, %2};"
                 :: "l"(&g_acc0[2 * d]), "f"(v.x), "f"(v.y) : "memory");
    atomicAdd(&g_cnt[d], 1.0f);
}

// ---------------- layer 0 combine + LN: warp per node ----------------
__global__ void __launch_bounds__(256) k_combine0(int n, const float* __restrict__ Wl,
        const float* __restrict__ bl, const float* __restrict__ Wr,
        const float* __restrict__ lnw, const float* __restrict__ lnb) {
    int i = (blockIdx.x * 256 + threadIdx.x) >> 5;
    int lane = threadIdx.x & 31;
    if (i >= n) return;
    float invc = 1.0f / fmaxf(g_cnt[i], 1.0f);
    if (lane == 0) g_inv[i] = invc;
    float m0 = g_acc0[2 * i] * invc, m1 = g_acc0[2 * i + 1] * invc;
    float p0 = g_xp0[2 * i], p1 = g_xp0[2 * i + 1];
    float v[4]; float s = 0.f;
#pragma unroll
    for (int k = 0; k < 4; k++) {
        int c = lane + 32 * k;
        v[k] = fmaf(m0, Wl[c], fmaf(m1, Wl[HH + c],
               fmaf(p0, Wr[c], fmaf(p1, Wr[HH + c], bl[c]))));
        s += v[k];
    }
    s = warp_sum(s);
    float mu = s * (1.f / HH);
    float q = 0.f;
#pragma unroll
    for (int k = 0; k < 4; k++) { v[k] -= mu; q += v[k] * v[k]; }
    q = warp_sum(q);
    float rstd = rsqrtf(q * (1.f / HH) + 1e-5f);
    size_t base = (size_t)i * HH;
#pragma unroll
    for (int k = 0; k < 4; k++) {
        int c = lane + 32 * k;
        g_h[base + c] = v[k] * rstd * lnw[c] + lnb[c];
    }
}

// =================== GEMM core (64x128x16, 256 thr, 8x4/thread) ===================
// tr=t>>5 (warp id, rows tr*8..tr*8+8), tc=t&31 (cols tc*4..tc*4+4)
// A stage: ar=t>>2 (0..63), ac=(t&3)*4  — LDG float4, transposed STS (x scale)
// W stage: wrow=t>>5 & +8, wcol=(t&31)*4 — cp.async 16B direct

#define GEMM_COMPUTE(cur)                                                     \
    _Pragma("unroll")                                                         \
    for (int kk = 0; kk < BK; kk++) {                                         \
        float4 a0 = *(const float4*)&As[cur][kk][tr * 8];                     \
        float4 a1 = *(const float4*)&As[cur][kk][tr * 8 + 4];                 \
        float4 wv = *(const float4*)&Ws[cur][kk][tc * 4];                     \
        float a[8] = {a0.x, a0.y, a0.z, a0.w, a1.x, a1.y, a1.z, a1.w};        \
        float w[4] = {wv.x, wv.y, wv.z, wv.w};                                \
        _Pragma("unroll")                                                     \
        for (int i = 0; i < 8; i++)                                           \
            _Pragma("unroll")                                                 \
            for (int j = 0; j < 4; j++)                                       \
                acc[i][j] = fmaf(a[i], w[j], acc[i][j]);                      \
    }

#define STS_A(buf, sc)                                                        \
    {                                                                         \
        As[buf][ac + 0][ar] = pa.x * sc; As[buf][ac + 1][ar] = pa.y * sc;     \
        As[buf][ac + 2][ar] = pa.z * sc; As[buf][ac + 3][ar] = pa.w * sc;     \
    }

#define CP_W(buf, Wptr)                                                       \
    {                                                                         \
        cp16(&Ws[buf][wrow][wcol], Wptr + (size_t)wrow * HH + wcol);          \
        cp16(&Ws[buf][wrow + 8][wcol], Wptr + (size_t)(wrow + 8) * HH + wcol);\
        CP_COMMIT();                                                          \
    }

// ---------------- proj GEMM: xp = relu(h @ Wp + bp); zeroes acc ----------------
__global__ void __launch_bounds__(NTH, 3) k_proj(const float* __restrict__ W,
                                                 const float* __restrict__ bias) {
    __shared__ float As[2][BK][BM + 4];
    __shared__ float Ws[2][BK][BN];
    const int t = threadIdx.x;
    const int tr = t >> 5, tc = t & 31;
    const int row0 = blockIdx.x * BM;
    const int ar = t >> 2, ac = (t & 3) * 4;
    const int wrow = t >> 5, wcol = (t & 31) * 4;
    const float* Abase = &g_h[(size_t)(row0 + ar) * HH];

    float4 pa = *(const float4*)(Abase + ac);
    STS_A(0, 1.0f);
    CP_W(0, W);

    float acc[8][4];
#pragma unroll
    for (int i = 0; i < 8; i++)
#pragma unroll
        for (int j = 0; j < 4; j++) acc[i][j] = 0.f;

    const int NT = HH / BK;  // 8
#pragma unroll
    for (int it = 0; it < NT; it++) {
        int cur = it & 1;
        CP_WAIT0();
        __syncthreads();
        if (it + 1 < NT) {
            int k0 = (it + 1) * BK;
            pa = *(const float4*)(Abase + k0 + ac);
            CP_W(cur ^ 1, W + (size_t)k0 * HH);
        }
        GEMM_COMPUTE(cur)
        if (it + 1 < NT) STS_A(cur ^ 1, 1.0f);
    }

    float b[4];
#pragma unroll
    for (int j = 0; j < 4; j++) b[j] = bias[tc * 4 + j];
    const float4 z = make_float4(0.f, 0.f, 0.f, 0.f);
#pragma unroll
    for (int i = 0; i < 8; i++) {
        size_t base = (size_t)(row0 + tr * 8 + i) * HH + tc * 4;
        float4 o;
        o.x = fmaxf(acc[i][0] + b[0], 0.f); o.y = fmaxf(acc[i][1] + b[1], 0.f);
        o.z = fmaxf(acc[i][2] + b[2], 0.f); o.w = fmaxf(acc[i][3] + b[3], 0.f);
        *(float4*)&g_xp[base] = o;
        *(float4*)&g_acc[base] = z;
    }
}

// ---------------- heavy aggregation: warp per edge ----------------
__global__ void __launch_bounds__(256) k_agg(const int* __restrict__ ei, int E) {
    int gw = (blockIdx.x * 256 + threadIdx.x) >> 5;
    int lane = threadIdx.x & 31;
    if (gw >= E) return;
    int s = ei[gw], d = ei[E + gw];
    float4 v = *(const float4*)&g_xp[(size_t)s * HH + lane * 4];
    float* p = &g_acc[(size_t)d * HH + lane * 4];
    asm volatile("red.global.add.v4.f32 [%0], {%1, %2, %3, %4};"
                 :: "l"(p), "f"(v.x), "f"(v.y), "f"(v.z), "f"(v.w) : "memory");
}

// ---------------- combine GEMM (K=256) + fused LN ----------------
__global__ void __launch_bounds__(NTH, 3) k_combine(const float* __restrict__ Wl,
        const float* __restrict__ Wr, const float* __restrict__ bl,
        const float* __restrict__ lnw, const float* __restrict__ lnb) {
    __shared__ float As[2][BK][BM + 4];
    __shared__ float Ws[2][BK][BN];
    const int t = threadIdx.x;
    const int tr = t >> 5, tc = t & 31;
    const int row0 = blockIdx.x * BM;
    const int ar = t >> 2, ac = (t & 3) * 4;
    const int wrow = t >> 5, wcol = (t & 31) * 4;
    const float invr = g_inv[row0 + ar];
    const float* Aa = &g_acc[(size_t)(row0 + ar) * HH];
    const float* Ax = &g_xp[(size_t)(row0 + ar) * HH];

    float4 pa = *(const float4*)(Aa + ac);
    STS_A(0, invr);
    CP_W(0, Wl);

    float acc[8][4];
#pragma unroll
    for (int i = 0; i < 8; i++)
#pragma unroll
        for (int j = 0; j < 4; j++) acc[i][j] = 0.f;

    const int NT = 2 * HH / BK;  // 16
    float nsc = invr;
#pragma unroll
    for (int it = 0; it < NT; it++) {
        int cur = it & 1;
        CP_WAIT0();
        __syncthreads();
        if (it + 1 < NT) {
            int nx = it + 1;
            const float* Ap; const float* Wn;
            if (nx < 8) { Ap = Aa + nx * BK; Wn = Wl + (size_t)nx * BK * HH; nsc = invr; }
            else        { Ap = Ax + (nx - 8) * BK; Wn = Wr + (size_t)(nx - 8) * BK * HH; nsc = 1.0f; }
            pa = *(const float4*)(Ap + ac);
            CP_W(cur ^ 1, Wn);
        }
        GEMM_COMPUTE(cur)
        if (it + 1 < NT) STS_A(cur ^ 1, nsc);
    }

    float b[4], lw[4], lb2[4];
#pragma unroll
    for (int j = 0; j < 4; j++) {
        b[j] = bl[tc * 4 + j]; lw[j] = lnw[tc * 4 + j]; lb2[j] = lnb[tc * 4 + j];
    }
#pragma unroll
    for (int i = 0; i < 8; i++) {
        float v[4]; float s = 0.f;
#pragma unroll
        for (int j = 0; j < 4; j++) { v[j] = acc[i][j] + b[j]; s += v[j]; }
        s = warp_sum(s);
        float mu = s * (1.f / HH);
        float q = 0.f;
#pragma unroll
        for (int j = 0; j < 4; j++) { v[j] -= mu; q += v[j] * v[j]; }
        q = warp_sum(q);
        float rstd = rsqrtf(q * (1.f / HH) + 1e-5f);
        float4 o;
        o.x = v[0] * rstd * lw[0] + lb2[0]; o.y = v[1] * rstd * lw[1] + lb2[1];
        o.z = v[2] * rstd * lw[2] + lb2[2]; o.w = v[3] * rstd * lw[3] + lb2[3];
        *(float4*)&g_h[(size_t)(row0 + tr * 8 + i) * HH + tc * 4] = o;
    }
}

// ---------------- edge MLP: gather-GEMM (K=256) + fused W2 reduction ----------------
__global__ void __launch_bounds__(NTH, 3) k_edgemlp(const int* __restrict__ eli, int Q,
        const float* __restrict__ W1, const float* __restrict__ b1,
        const float* __restrict__ W2, const float* __restrict__ b2,
        float* __restrict__ out) {
    __shared__ float As[2][BK][BM + 4];
    __shared__ float Ws[2][BK][BN];
    __shared__ int sbase[BM], dbase[BM];
    const int t = threadIdx.x;
    const int tr = t >> 5, tc = t & 31;
    const int q0 = blockIdx.x * BM;
    const int ar = t >> 2, ac = (t & 3) * 4;
    const int wrow = t >> 5, wcol = (t & 31) * 4;

    if (t < BM) {
        int q = q0 + t, s = 0, d = 0;
        if (q < Q) { s = eli[q]; d = eli[Q + q]; }
        sbase[t] = s * HH; dbase[t] = d * HH;
    }
    __syncthreads();
    const float* Asrc = &g_h[(size_t)sbase[ar]];
    const float* Adst = &g_h[(size_t)dbase[ar]];

    float4 pa = *(const float4*)(Asrc + ac);
    STS_A(0, 1.0f);
    CP_W(0, W1);

    float acc[8][4];
#pragma unroll
    for (int i = 0; i < 8; i++)
#pragma unroll
        for (int j = 0; j < 4; j++) acc[i][j] = 0.f;

    const int NT = 2 * HH / BK;  // 16
#pragma unroll
    for (int it = 0; it < NT; it++) {
        int cur = it & 1;
        CP_WAIT0();
        __syncthreads();
        if (it + 1 < NT) {
            int nx = it + 1;
            const float* Ap = (nx < 8) ? (Asrc + nx * BK) : (Adst + (nx - 8) * BK);
            pa = *(const float4*)(Ap + ac);
            CP_W(cur ^ 1, W1 + (size_t)nx * BK * HH);
        }
        GEMM_COMPUTE(cur)
        if (it + 1 < NT) STS_A(cur ^ 1, 1.0f);
    }

    float b[4], w2[4];
#pragma unroll
    for (int j = 0; j < 4; j++) { b[j] = b1[tc * 4 + j]; w2[j] = W2[tc * 4 + j]; }
    float b2v = b2[0];
#pragma unroll
    for (int i = 0; i < 8; i++) {
        float s = 0.f;
#pragma unroll
        for (int j = 0; j < 4; j++)
            s = fmaf(fmaxf(acc[i][j] + b[j], 0.f), w2[j], s);
        s = warp_sum(s);
        int q = q0 + tr * 8 + i;
        if (tc == 0 && q < Q) out[q] = s + b2v;
    }
}

// ---------------- host launch ----------------
extern "C" void kernel_launch(void* const* d_in, const int* in_sizes, int n_in,
                              void* d_out, int out_size) {
    const float* x    = (const float*)d_in[0];
    const int*   ei   = (const int*)d_in[1];
    const int*   eli  = (const int*)d_in[2];
    const float* p0Wp = (const float*)d_in[3];
    const float* p0bp = (const float*)d_in[4];
    const float* p0Wl = (const float*)d_in[5];
    const float* p0bl = (const float*)d_in[6];
    const float* p0Wr = (const float*)d_in[7];
    const float* Wp_s = (const float*)d_in[8];
    const float* bp_s = (const float*)d_in[9];
    const float* Wl_s = (const float*)d_in[10];
    const float* bl_s = (const float*)d_in[11];
    const float* Wr_s = (const float*)d_in[12];
    const float* ln_w = (const float*)d_in[13];
    const float* ln_b = (const float*)d_in[14];
    const float* eW1  = (const float*)d_in[15];
    const float* eb1  = (const float*)d_in[16];
    const float* eW2  = (const float*)d_in[17];
    const float* eb2  = (const float*)d_in[18];
    float* out = (float*)d_out;

    const int n = in_sizes[0] / 2;
    const int E = in_sizes[1] / 2;
    const int Q = in_sizes[2] / 2;

    void *acc0p = nullptr, *cntp = nullptr;
    cudaGetSymbolAddress(&acc0p, g_acc0);
    cudaGetSymbolAddress(&cntp, g_cnt);
    cudaMemsetAsync(acc0p, 0, (size_t)n * 2 * sizeof(float));
    cudaMemsetAsync(cntp, 0, (size_t)n * sizeof(float));

    k_l0<<<(n + 255) / 256, 256>>>(x, p0Wp, p0bp, n);
    k_agg0<<<(E + 255) / 256, 256>>>(ei, E);
    k_combine0<<<(n * 32 + 255) / 256, 256>>>(n, p0Wl, p0bl, p0Wr, ln_w, ln_b);

    const int gb = (n + BM - 1) / BM;   // 1563
    const long long aggThreads = (long long)E * 32;
    const int aggBlocks = (int)((aggThreads + 255) / 256);
    for (int l = 0; l < 2; l++) {
        k_proj<<<gb, NTH>>>(Wp_s + (size_t)l * HH * HH, bp_s + (size_t)l * HH);
        k_agg<<<aggBlocks, 256>>>(ei, E);
        k_combine<<<gb, NTH>>>(Wl_s + (size_t)l * HH * HH, Wr_s + (size_t)l * HH * HH,
                               bl_s + (size_t)l * HH,
                               ln_w + (size_t)(l + 1) * HH, ln_b + (size_t)(l + 1) * HH);
    }
    k_edgemlp<<<(Q + BM - 1) / BM, NTH>>>(eli, Q, eW1, eb1, eW2, eb2, out);
}

// round 4
// speedup vs baseline: 1.9396x; 1.3593x over previous
#include <cuda_runtime.h>
#include <cstdint>

#define HH 128
#define NPAD 100096
#define EMAX 1600000
#define BM 64
#define BN 128
#define BK 16
#define NTH 256
#define SCAN_B 512

// ---------------- scratch ----------------
__device__ float g_xp [NPAD * HH];
__device__ float g_acc[NPAD * HH];     // holds MEAN-aggregated features
__device__ float g_h  [NPAD * HH];
__device__ float g_xp0[NPAD * 2];
__device__ int   g_deg [NPAD];
__device__ int   g_off [NPAD + 1];
__device__ int   g_cur [NPAD];
__device__ int   g_srcs[EMAX];
__device__ int   g_bsum [4096];
__device__ int   g_bsumx[4096];

__device__ __forceinline__ float warp_sum(float v) {
#pragma unroll
    for (int o = 16; o > 0; o >>= 1) v += __shfl_xor_sync(0xffffffffu, v, o);
    return v;
}

__device__ __forceinline__ void cp16(void* dst, const void* src) {
    uint32_t d = (uint32_t)__cvta_generic_to_shared(dst);
    asm volatile("cp.async.ca.shared.global [%0], [%1], 16;" :: "r"(d), "l"(src));
}
#define CP_COMMIT() asm volatile("cp.async.commit_group;")
#define CP_WAIT0()  asm volatile("cp.async.wait_group 0;" ::: "memory")

// ================= CSR build =================
__global__ void k_hist(const int* __restrict__ ei, int E) {
    int e = blockIdx.x * blockDim.x + threadIdx.x;
    if (e >= E) return;
    atomicAdd(&g_deg[ei[E + e]], 1);
}

// block-wise exclusive scan (512 per block)
__global__ void __launch_bounds__(SCAN_B) k_scan1(int n) {
    __shared__ int sm[SCAN_B];
    int t = threadIdx.x;
    int idx = blockIdx.x * SCAN_B + t;
    int v = (idx < n) ? g_deg[idx] : 0;
    sm[t] = v;
    __syncthreads();
#pragma unroll
    for (int off = 1; off < SCAN_B; off <<= 1) {
        int add = (t >= off) ? sm[t - off] : 0;
        __syncthreads();
        sm[t] += add;
        __syncthreads();
    }
    if (idx < n) g_off[idx] = sm[t] - v;   // exclusive
    if (t == SCAN_B - 1) g_bsum[blockIdx.x] = sm[t];
}

__global__ void __launch_bounds__(1024) k_scan2(int nb) {
    __shared__ int sm[1024];
    int t = threadIdx.x;
    int v = (t < nb) ? g_bsum[t] : 0;
    sm[t] = v;
    __syncthreads();
#pragma unroll
    for (int off = 1; off < 1024; off <<= 1) {
        int add = (t >= off) ? sm[t - off] : 0;
        __syncthreads();
        sm[t] += add;
        __syncthreads();
    }
    if (t < nb) g_bsumx[t] = sm[t] - v;    // exclusive block offsets
}

__global__ void k_scan3(int n, int E) {
    int idx = blockIdx.x * blockDim.x + threadIdx.x;
    if (idx == 0) g_off[n] = E;
    if (idx >= n) return;
    int o = g_off[idx] + g_bsumx[idx / SCAN_B];
    g_off[idx] = o;
    g_cur[idx] = o;
}

__global__ void k_scatter(const int* __restrict__ ei, int E) {
    int e = blockIdx.x * blockDim.x + threadIdx.x;
    if (e >= E) return;
    int s = ei[e], d = ei[E + e];
    int pos = atomicAdd(&g_cur[d], 1);
    g_srcs[pos] = s;
}

// ================= layer 0 =================
__global__ void k_l0(const float* __restrict__ x, const float* __restrict__ Wp,
                     const float* __restrict__ bp, int n) {
    int i = blockIdx.x * blockDim.x + threadIdx.x;
    if (i >= n) return;
    float x0 = x[2 * i], x1 = x[2 * i + 1];
    float a = fmaxf(fmaf(x0, Wp[0], fmaf(x1, Wp[2], bp[0])), 0.f);
    float b = fmaxf(fmaf(x0, Wp[1], fmaf(x1, Wp[3], bp[1])), 0.f);
    g_xp0[2 * i] = a;
    g_xp0[2 * i + 1] = b;
}

// fused: CSR mean-gather (dim 2) + combine + LN; warp per node
__global__ void __launch_bounds__(256) k_combine0(int n, const float* __restrict__ Wl,
        const float* __restrict__ bl, const float* __restrict__ Wr,
        const float* __restrict__ lnw, const float* __restrict__ lnb) {
    int node = (blockIdx.x * 256 + threadIdx.x) >> 5;
    int lane = threadIdx.x & 31;
    if (node >= n) return;
    int beg = g_off[node], end = g_off[node + 1];
    float m0 = 0.f, m1 = 0.f;
    for (int j = beg + lane; j < end; j += 32) {
        int s = __ldg(&g_srcs[j]);
        float2 v = *(const float2*)&g_xp0[2 * s];
        m0 += v.x; m1 += v.y;
    }
    m0 = warp_sum(m0); m1 = warp_sum(m1);
    float inv = 1.f / fmaxf((float)(end - beg), 1.f);
    m0 *= inv; m1 *= inv;
    float p0 = g_xp0[2 * node], p1 = g_xp0[2 * node + 1];
    float v[4]; float s = 0.f;
#pragma unroll
    for (int k = 0; k < 4; k++) {
        int c = lane + 32 * k;
        v[k] = fmaf(m0, Wl[c], fmaf(m1, Wl[HH + c],
               fmaf(p0, Wr[c], fmaf(p1, Wr[HH + c], bl[c]))));
        s += v[k];
    }
    s = warp_sum(s);
    float mu = s * (1.f / HH);
    float q = 0.f;
#pragma unroll
    for (int k = 0; k < 4; k++) { v[k] -= mu; q += v[k] * v[k]; }
    q = warp_sum(q);
    float rstd = rsqrtf(q * (1.f / HH) + 1e-5f);
    size_t base = (size_t)node * HH;
#pragma unroll
    for (int k = 0; k < 4; k++) {
        int c = lane + 32 * k;
        g_h[base + c] = v[k] * rstd * lnw[c] + lnb[c];
    }
}

// ================= heavy aggregation: CSR gather-reduce, warp per node =================
__global__ void __launch_bounds__(256) k_gagg(int n) {
    int node = (blockIdx.x * 256 + threadIdx.x) >> 5;
    int lane = threadIdx.x & 31;
    if (node >= n) return;
    int beg = g_off[node], end = g_off[node + 1];
    float4 a = make_float4(0.f, 0.f, 0.f, 0.f);
    int j = beg;
    for (; j + 2 <= end; j += 2) {
        int s0 = __ldg(&g_srcs[j]);
        int s1 = __ldg(&g_srcs[j + 1]);
        float4 v0 = *(const float4*)&g_xp[(size_t)s0 * HH + lane * 4];
        float4 v1 = *(const float4*)&g_xp[(size_t)s1 * HH + lane * 4];
        a.x += v0.x + v1.x; a.y += v0.y + v1.y;
        a.z += v0.z + v1.z; a.w += v0.w + v1.w;
    }
    if (j < end) {
        int s0 = __ldg(&g_srcs[j]);
        float4 v0 = *(const float4*)&g_xp[(size_t)s0 * HH + lane * 4];
        a.x += v0.x; a.y += v0.y; a.z += v0.z; a.w += v0.w;
    }
    float inv = 1.f / fmaxf((float)(end - beg), 1.f);
    a.x *= inv; a.y *= inv; a.z *= inv; a.w *= inv;
    *(float4*)&g_acc[(size_t)node * HH + lane * 4] = a;
}

// =================== GEMM core (64x128x16, 256 thr, 8x4/thread) ===================
#define GEMM_COMPUTE(cur)                                                     \
    _Pragma("unroll")                                                         \
    for (int kk = 0; kk < BK; kk++) {                                         \
        float4 a0 = *(const float4*)&As[cur][kk][tr * 8];                     \
        float4 a1 = *(const float4*)&As[cur][kk][tr * 8 + 4];                 \
        float4 wv = *(const float4*)&Ws[cur][kk][tc * 4];                     \
        float a[8] = {a0.x, a0.y, a0.z, a0.w, a1.x, a1.y, a1.z, a1.w};        \
        float w[4] = {wv.x, wv.y, wv.z, wv.w};                                \
        _Pragma("unroll")                                                     \
        for (int i = 0; i < 8; i++)                                           \
            _Pragma("unroll")                                                 \
            for (int j = 0; j < 4; j++)                                       \
                acc[i][j] = fmaf(a[i], w[j], acc[i][j]);                      \
    }

#define STS_A(buf)                                                            \
    {                                                                         \
        As[buf][ac + 0][ar] = pa.x; As[buf][ac + 1][ar] = pa.y;               \
        As[buf][ac + 2][ar] = pa.z; As[buf][ac + 3][ar] = pa.w;               \
    }

#define CP_W(buf, Wptr)                                                       \
    {                                                                         \
        cp16(&Ws[buf][wrow][wcol], Wptr + (size_t)wrow * HH + wcol);          \
        cp16(&Ws[buf][wrow + 8][wcol], Wptr + (size_t)(wrow + 8) * HH + wcol);\
        CP_COMMIT();                                                          \
    }

// ---------------- proj GEMM: xp = relu(h @ Wp + bp) ----------------
__global__ void __launch_bounds__(NTH, 3) k_proj(const float* __restrict__ W,
                                                 const float* __restrict__ bias) {
    __shared__ float As[2][BK][BM + 4];
    __shared__ float Ws[2][BK][BN];
    const int t = threadIdx.x;
    const int tr = t >> 5, tc = t & 31;
    const int row0 = blockIdx.x * BM;
    const int ar = t >> 2, ac = (t & 3) * 4;
    const int wrow = t >> 5, wcol = (t & 31) * 4;
    const float* Abase = &g_h[(size_t)(row0 + ar) * HH];

    float4 pa = *(const float4*)(Abase + ac);
    STS_A(0);
    CP_W(0, W);

    float acc[8][4];
#pragma unroll
    for (int i = 0; i < 8; i++)
#pragma unroll
        for (int j = 0; j < 4; j++) acc[i][j] = 0.f;

    const int NT = HH / BK;  // 8
#pragma unroll
    for (int it = 0; it < NT; it++) {
        int cur = it & 1;
        CP_WAIT0();
        __syncthreads();
        if (it + 1 < NT) {
            int k0 = (it + 1) * BK;
            pa = *(const float4*)(Abase + k0 + ac);
            CP_W(cur ^ 1, W + (size_t)k0 * HH);
        }
        GEMM_COMPUTE(cur)
        if (it + 1 < NT) STS_A(cur ^ 1);
    }

    float b[4];
#pragma unroll
    for (int j = 0; j < 4; j++) b[j] = bias[tc * 4 + j];
#pragma unroll
    for (int i = 0; i < 8; i++) {
        float4 o;
        o.x = fmaxf(acc[i][0] + b[0], 0.f); o.y = fmaxf(acc[i][1] + b[1], 0.f);
        o.z = fmaxf(acc[i][2] + b[2], 0.f); o.w = fmaxf(acc[i][3] + b[3], 0.f);
        *(float4*)&g_xp[(size_t)(row0 + tr * 8 + i) * HH + tc * 4] = o;
    }
}

// ---------------- combine GEMM (K=256: mean | xp) + fused LN ----------------
__global__ void __launch_bounds__(NTH, 3) k_combine(const float* __restrict__ Wl,
        const float* __restrict__ Wr, const float* __restrict__ bl,
        const float* __restrict__ lnw, const float* __restrict__ lnb) {
    __shared__ float As[2][BK][BM + 4];
    __shared__ float Ws[2][BK][BN];
    const int t = threadIdx.x;
    const int tr = t >> 5, tc = t & 31;
    const int row0 = blockIdx.x * BM;
    const int ar = t >> 2, ac = (t & 3) * 4;
    const int wrow = t >> 5, wcol = (t & 31) * 4;
    const float* Aa = &g_acc[(size_t)(row0 + ar) * HH];
    const float* Ax = &g_xp[(size_t)(row0 + ar) * HH];

    float4 pa = *(const float4*)(Aa + ac);
    STS_A(0);
    CP_W(0, Wl);

    float acc[8][4];
#pragma unroll
    for (int i = 0; i < 8; i++)
#pragma unroll
        for (int j = 0; j < 4; j++) acc[i][j] = 0.f;

    const int NT = 2 * HH / BK;  // 16
#pragma unroll
    for (int it = 0; it < NT; it++) {
        int cur = it & 1;
        CP_WAIT0();
        __syncthreads();
        if (it + 1 < NT) {
            int nx = it + 1;
            const float* Ap; const float* Wn;
            if (nx < 8) { Ap = Aa + nx * BK; Wn = Wl + (size_t)nx * BK * HH; }
            else        { Ap = Ax + (nx - 8) * BK; Wn = Wr + (size_t)(nx - 8) * BK * HH; }
            pa = *(const float4*)(Ap + ac);
            CP_W(cur ^ 1, Wn);
        }
        GEMM_COMPUTE(cur)
        if (it + 1 < NT) STS_A(cur ^ 1);
    }

    float b[4], lw[4], lb2[4];
#pragma unroll
    for (int j = 0; j < 4; j++) {
        b[j] = bl[tc * 4 + j]; lw[j] = lnw[tc * 4 + j]; lb2[j] = lnb[tc * 4 + j];
    }
#pragma unroll
    for (int i = 0; i < 8; i++) {
        float v[4]; float s = 0.f;
#pragma unroll
        for (int j = 0; j < 4; j++) { v[j] = acc[i][j] + b[j]; s += v[j]; }
        s = warp_sum(s);
        float mu = s * (1.f / HH);
        float q = 0.f;
#pragma unroll
        for (int j = 0; j < 4; j++) { v[j] -= mu; q += v[j] * v[j]; }
        q = warp_sum(q);
        float rstd = rsqrtf(q * (1.f / HH) + 1e-5f);
        float4 o;
        o.x = v[0] * rstd * lw[0] + lb2[0]; o.y = v[1] * rstd * lw[1] + lb2[1];
        o.z = v[2] * rstd * lw[2] + lb2[2]; o.w = v[3] * rstd * lw[3] + lb2[3];
        *(float4*)&g_h[(size_t)(row0 + tr * 8 + i) * HH + tc * 4] = o;
    }
}

// ---------------- edge MLP: gather-GEMM (K=256) + fused W2 reduction ----------------
__global__ void __launch_bounds__(NTH, 3) k_edgemlp(const int* __restrict__ eli, int Q,
        const float* __restrict__ W1, const float* __restrict__ b1,
        const float* __restrict__ W2, const float* __restrict__ b2,
        float* __restrict__ out) {
    __shared__ float As[2][BK][BM + 4];
    __shared__ float Ws[2][BK][BN];
    __shared__ int sbase[BM], dbase[BM];
    const int t = threadIdx.x;
    const int tr = t >> 5, tc = t & 31;
    const int q0 = blockIdx.x * BM;
    const int ar = t >> 2, ac = (t & 3) * 4;
    const int wrow = t >> 5, wcol = (t & 31) * 4;

    if (t < BM) {
        int q = q0 + t, s = 0, d = 0;
        if (q < Q) { s = eli[q]; d = eli[Q + q]; }
        sbase[t] = s * HH; dbase[t] = d * HH;
    }
    __syncthreads();
    const float* Asrc = &g_h[(size_t)sbase[ar]];
    const float* Adst = &g_h[(size_t)dbase[ar]];

    float4 pa = *(const float4*)(Asrc + ac);
    STS_A(0);
    CP_W(0, W1);

    float acc[8][4];
#pragma unroll
    for (int i = 0; i < 8; i++)
#pragma unroll
        for (int j = 0; j < 4; j++) acc[i][j] = 0.f;

    const int NT = 2 * HH / BK;  // 16
#pragma unroll
    for (int it = 0; it < NT; it++) {
        int cur = it & 1;
        CP_WAIT0();
        __syncthreads();
        if (it + 1 < NT) {
            int nx = it + 1;
            const float* Ap = (nx < 8) ? (Asrc + nx * BK) : (Adst + (nx - 8) * BK);
            pa = *(const float4*)(Ap + ac);
            CP_W(cur ^ 1, W1 + (size_t)nx * BK * HH);
        }
        GEMM_COMPUTE(cur)
        if (it + 1 < NT) STS_A(cur ^ 1);
    }

    float b[4], w2[4];
#pragma unroll
    for (int j = 0; j < 4; j++) { b[j] = b1[tc * 4 + j]; w2[j] = W2[tc * 4 + j]; }
    float b2v = b2[0];
#pragma unroll
    for (int i = 0; i < 8; i++) {
        float s = 0.f;
#pragma unroll
        for (int j = 0; j < 4; j++)
            s = fmaf(fmaxf(acc[i][j] + b[j], 0.f), w2[j], s);
        s = warp_sum(s);
        int q = q0 + tr * 8 + i;
        if (tc == 0 && q < Q) out[q] = s + b2v;
    }
}

// ---------------- host launch ----------------
extern "C" void kernel_launch(void* const* d_in, const int* in_sizes, int n_in,
                              void* d_out, int out_size) {
    const float* x    = (const float*)d_in[0];
    const int*   ei   = (const int*)d_in[1];
    const int*   eli  = (const int*)d_in[2];
    const float* p0Wp = (const float*)d_in[3];
    const float* p0bp = (const float*)d_in[4];
    const float* p0Wl = (const float*)d_in[5];
    const float* p0bl = (const float*)d_in[6];
    const float* p0Wr = (const float*)d_in[7];
    const float* Wp_s = (const float*)d_in[8];
    const float* bp_s = (const float*)d_in[9];
    const float* Wl_s = (const float*)d_in[10];
    const float* bl_s = (const float*)d_in[11];
    const float* Wr_s = (const float*)d_in[12];
    const float* ln_w = (const float*)d_in[13];
    const float* ln_b = (const float*)d_in[14];
    const float* eW1  = (const float*)d_in[15];
    const float* eb1  = (const float*)d_in[16];
    const float* eW2  = (const float*)d_in[17];
    const float* eb2  = (const float*)d_in[18];
    float* out = (float*)d_out;

    const int n = in_sizes[0] / 2;
    const int E = in_sizes[1] / 2;
    const int Q = in_sizes[2] / 2;

    // ---- CSR build (once; reused by all 3 aggregations) ----
    void* degp = nullptr;
    cudaGetSymbolAddress(&degp, g_deg);
    cudaMemsetAsync(degp, 0, (size_t)n * sizeof(int));
    k_hist<<<(E + 255) / 256, 256>>>(ei, E);
    const int nb = (n + SCAN_B - 1) / SCAN_B;
    k_scan1<<<nb, SCAN_B>>>(n);
    k_scan2<<<1, 1024>>>(nb);
    k_scan3<<<(n + 255) / 256, 256>>>(n, E);
    k_scatter<<<(E + 255) / 256, 256>>>(ei, E);

    // ---- layer 0 ----
    k_l0<<<(n + 255) / 256, 256>>>(x, p0Wp, p0bp, n);
    k_combine0<<<(n * 32 + 255) / 256, 256>>>(n, p0Wl, p0bl, p0Wr, ln_w, ln_b);

    // ---- layers 1..2 ----
    const int gb = (n + BM - 1) / BM;
    const int gaggB = (n * 32 + 255) / 256;
    for (int l = 0; l < 2; l++) {
        k_proj<<<gb, NTH>>>(Wp_s + (size_t)l * HH * HH, bp_s + (size_t)l * HH);
        k_gagg<<<gaggB, 256>>>(n);
        k_combine<<<gb, NTH>>>(Wl_s + (size_t)l * HH * HH, Wr_s + (size_t)l * HH * HH,
                               bl_s + (size_t)l * HH,
                               ln_w + (size_t)(l + 1) * HH, ln_b + (size_t)(l + 1) * HH);
    }
    k_edgemlp<<<(Q + BM - 1) / BM, NTH>>>(eli, Q, eW1, eb1, eW2, eb2, out);
}

// round 5
// speedup vs baseline: 1.9416x; 1.0010x over previous
#include <cuda_runtime.h>
#include <cstdint>

#define HH 128
#define NPAD 100096
#define EMAX 1600000
#define BM 64
#define BN 128
#define BK 16
#define NTH 256
#define SCAN_B 512

// ---------------- scratch ----------------
__device__ float g_xp [NPAD * HH];
__device__ float g_acc[NPAD * HH];     // holds MEAN-aggregated features
__device__ float g_h  [NPAD * HH];
__device__ float g_xp0[NPAD * 2];
__device__ int   g_deg [NPAD];
__device__ int   g_off [NPAD + 1];
__device__ int   g_cur [NPAD];
__device__ int   g_srcs[EMAX];
__device__ int   g_bsum [4096];
__device__ int   g_bsumx[4096];

__device__ __forceinline__ float warp_sum(float v) {
#pragma unroll
    for (int o = 16; o > 0; o >>= 1) v += __shfl_xor_sync(0xffffffffu, v, o);
    return v;
}

__device__ __forceinline__ void cp16(void* dst, const void* src) {
    uint32_t d = (uint32_t)__cvta_generic_to_shared(dst);
    asm volatile("cp.async.ca.shared.global [%0], [%1], 16;" :: "r"(d), "l"(src));
}
#define CP_COMMIT() asm volatile("cp.async.commit_group;")
#define CP_WAIT0()  asm volatile("cp.async.wait_group 0;" ::: "memory")

// ================= CSR build =================
__global__ void k_hist(const int* __restrict__ ei, int E) {
    int e = blockIdx.x * blockDim.x + threadIdx.x;
    if (e >= E) return;
    atomicAdd(&g_deg[ei[E + e]], 1);
}

// block-wise exclusive scan (512 per block)
__global__ void __launch_bounds__(SCAN_B) k_scan1(int n) {
    __shared__ int sm[SCAN_B];
    int t = threadIdx.x;
    int idx = blockIdx.x * SCAN_B + t;
    int v = (idx < n) ? g_deg[idx] : 0;
    sm[t] = v;
    __syncthreads();
#pragma unroll
    for (int off = 1; off < SCAN_B; off <<= 1) {
        int add = (t >= off) ? sm[t - off] : 0;
        __syncthreads();
        sm[t] += add;
        __syncthreads();
    }
    if (idx < n) g_off[idx] = sm[t] - v;   // exclusive
    if (t == SCAN_B - 1) g_bsum[blockIdx.x] = sm[t];
}

__global__ void __launch_bounds__(1024) k_scan2(int nb) {
    __shared__ int sm[1024];
    int t = threadIdx.x;
    int v = (t < nb) ? g_bsum[t] : 0;
    sm[t] = v;
    __syncthreads();
#pragma unroll
    for (int off = 1; off < 1024; off <<= 1) {
        int add = (t >= off) ? sm[t - off] : 0;
        __syncthreads();
        sm[t] += add;
        __syncthreads();
    }
    if (t < nb) g_bsumx[t] = sm[t] - v;    // exclusive block offsets
}

__global__ void k_scan3(int n, int E) {
    int idx = blockIdx.x * blockDim.x + threadIdx.x;
    if (idx == 0) g_off[n] = E;
    if (idx >= n) return;
    int o = g_off[idx] + g_bsumx[idx / SCAN_B];
    g_off[idx] = o;
    g_cur[idx] = o;
}

__global__ void k_scatter(const int* __restrict__ ei, int E) {
    int e = blockIdx.x * blockDim.x + threadIdx.x;
    if (e >= E) return;
    int s = ei[e], d = ei[E + e];
    int pos = atomicAdd(&g_cur[d], 1);
    g_srcs[pos] = s;
}

// ================= layer 0 =================
__global__ void k_l0(const float* __restrict__ x, const float* __restrict__ Wp,
                     const float* __restrict__ bp, int n) {
    int i = blockIdx.x * blockDim.x + threadIdx.x;
    if (i >= n) return;
    float x0 = x[2 * i], x1 = x[2 * i + 1];
    float a = fmaxf(fmaf(x0, Wp[0], fmaf(x1, Wp[2], bp[0])), 0.f);
    float b = fmaxf(fmaf(x0, Wp[1], fmaf(x1, Wp[3], bp[1])), 0.f);
    g_xp0[2 * i] = a;
    g_xp0[2 * i + 1] = b;
}

// fused: CSR mean-gather (dim 2) + combine + LN; warp per node
__global__ void __launch_bounds__(256) k_combine0(int n, const float* __restrict__ Wl,
        const float* __restrict__ bl, const float* __restrict__ Wr,
        const float* __restrict__ lnw, const float* __restrict__ lnb) {
    int node = (blockIdx.x * 256 + threadIdx.x) >> 5;
    int lane = threadIdx.x & 31;
    if (node >= n) return;
    int beg = g_off[node], end = g_off[node + 1];
    float m0 = 0.f, m1 = 0.f;
    for (int j = beg + lane; j < end; j += 32) {
        int s = __ldg(&g_srcs[j]);
        float2 v = *(const float2*)&g_xp0[2 * s];
        m0 += v.x; m1 += v.y;
    }
    m0 = warp_sum(m0); m1 = warp_sum(m1);
    float inv = 1.f / fmaxf((float)(end - beg), 1.f);
    m0 *= inv; m1 *= inv;
    float p0 = g_xp0[2 * node], p1 = g_xp0[2 * node + 1];
    float v[4]; float s = 0.f;
#pragma unroll
    for (int k = 0; k < 4; k++) {
        int c = lane + 32 * k;
        v[k] = fmaf(m0, Wl[c], fmaf(m1, Wl[HH + c],
               fmaf(p0, Wr[c], fmaf(p1, Wr[HH + c], bl[c]))));
        s += v[k];
    }
    s = warp_sum(s);
    float mu = s * (1.f / HH);
    float q = 0.f;
#pragma unroll
    for (int k = 0; k < 4; k++) { v[k] -= mu; q += v[k] * v[k]; }
    q = warp_sum(q);
    float rstd = rsqrtf(q * (1.f / HH) + 1e-5f);
    size_t base = (size_t)node * HH;
#pragma unroll
    for (int k = 0; k < 4; k++) {
        int c = lane + 32 * k;
        g_h[base + c] = v[k] * rstd * lnw[c] + lnb[c];
    }
}

// ================= heavy aggregation: CSR gather-reduce, warp per node =================
__global__ void __launch_bounds__(256) k_gagg(int n) {
    int node = (blockIdx.x * 256 + threadIdx.x) >> 5;
    int lane = threadIdx.x & 31;
    if (node >= n) return;
    int beg = g_off[node], end = g_off[node + 1];
    float4 a = make_float4(0.f, 0.f, 0.f, 0.f);
    int j = beg;
    for (; j + 2 <= end; j += 2) {
        int s0 = __ldg(&g_srcs[j]);
        int s1 = __ldg(&g_srcs[j + 1]);
        float4 v0 = *(const float4*)&g_xp[(size_t)s0 * HH + lane * 4];
        float4 v1 = *(const float4*)&g_xp[(size_t)s1 * HH + lane * 4];
        a.x += v0.x + v1.x; a.y += v0.y + v1.y;
        a.z += v0.z + v1.z; a.w += v0.w + v1.w;
    }
    if (j < end) {
        int s0 = __ldg(&g_srcs[j]);
        float4 v0 = *(const float4*)&g_xp[(size_t)s0 * HH + lane * 4];
        a.x += v0.x; a.y += v0.y; a.z += v0.z; a.w += v0.w;
    }
    float inv = 1.f / fmaxf((float)(end - beg), 1.f);
    a.x *= inv; a.y *= inv; a.z *= inv; a.w *= inv;
    *(float4*)&g_acc[(size_t)node * HH + lane * 4] = a;
}

// =================== GEMM core (64x128x16, 256 thr, 8x4/thread) ===================
#define GEMM_COMPUTE(cur)                                                     \
    _Pragma("unroll")                                                         \
    for (int kk = 0; kk < BK; kk++) {                                         \
        float4 a0 = *(const float4*)&As[cur][kk][tr * 8];                     \
        float4 a1 = *(const float4*)&As[cur][kk][tr * 8 + 4];                 \
        float4 wv = *(const float4*)&Ws[cur][kk][tc * 4];                     \
        float a[8] = {a0.x, a0.y, a0.z, a0.w, a1.x, a1.y, a1.z, a1.w};        \
        float w[4] = {wv.x, wv.y, wv.z, wv.w};                                \
        _Pragma("unroll")                                                     \
        for (int i = 0; i < 8; i++)                                           \
            _Pragma("unroll")                                                 \
            for (int j = 0; j < 4; j++)                                       \
                acc[i][j] = fmaf(a[i], w[j], acc[i][j]);                      \
    }

#define STS_A(buf)                                                            \
    {                                                                         \
        As[buf][ac + 0][ar] = pa.x; As[buf][ac + 1][ar] = pa.y;               \
        As[buf][ac + 2][ar] = pa.z; As[buf][ac + 3][ar] = pa.w;               \
    }

#define CP_W(buf, Wptr)                                                       \
    {                                                                         \
        cp16(&Ws[buf][wrow][wcol], Wptr + (size_t)wrow * HH + wcol);          \
        cp16(&Ws[buf][wrow + 8][wcol], Wptr + (size_t)(wrow + 8) * HH + wcol);\
        CP_COMMIT();                                                          \
    }

// ---------------- proj GEMM: xp = relu(h @ Wp + bp) ----------------
__global__ void __launch_bounds__(NTH, 3) k_proj(const float* __restrict__ W,
                                                 const float* __restrict__ bias) {
    __shared__ float As[2][BK][BM + 4];
    __shared__ float Ws[2][BK][BN];
    const int t = threadIdx.x;
    const int tr = t >> 5, tc = t & 31;
    const int row0 = blockIdx.x * BM;
    const int ar = t >> 2, ac = (t & 3) * 4;
    const int wrow = t >> 5, wcol = (t & 31) * 4;
    const float* Abase = &g_h[(size_t)(row0 + ar) * HH];

    float4 pa = *(const float4*)(Abase + ac);
    STS_A(0);
    CP_W(0, W);

    float acc[8][4];
#pragma unroll
    for (int i = 0; i < 8; i++)
#pragma unroll
        for (int j = 0; j < 4; j++) acc[i][j] = 0.f;

    const int NT = HH / BK;  // 8
#pragma unroll
    for (int it = 0; it < NT; it++) {
        int cur = it & 1;
        CP_WAIT0();
        __syncthreads();
        if (it + 1 < NT) {
            int k0 = (it + 1) * BK;
            pa = *(const float4*)(Abase + k0 + ac);
            CP_W(cur ^ 1, W + (size_t)k0 * HH);
        }
        GEMM_COMPUTE(cur)
        if (it + 1 < NT) STS_A(cur ^ 1);
    }

    float b[4];
#pragma unroll
    for (int j = 0; j < 4; j++) b[j] = bias[tc * 4 + j];
#pragma unroll
    for (int i = 0; i < 8; i++) {
        float4 o;
        o.x = fmaxf(acc[i][0] + b[0], 0.f); o.y = fmaxf(acc[i][1] + b[1], 0.f);
        o.z = fmaxf(acc[i][2] + b[2], 0.f); o.w = fmaxf(acc[i][3] + b[3], 0.f);
        *(float4*)&g_xp[(size_t)(row0 + tr * 8 + i) * HH + tc * 4] = o;
    }
}

// ---------------- combine GEMM (K=256: mean | xp) + fused LN ----------------
__global__ void __launch_bounds__(NTH, 3) k_combine(const float* __restrict__ Wl,
        const float* __restrict__ Wr, const float* __restrict__ bl,
        const float* __restrict__ lnw, const float* __restrict__ lnb) {
    __shared__ float As[2][BK][BM + 4];
    __shared__ float Ws[2][BK][BN];
    const int t = threadIdx.x;
    const int tr = t >> 5, tc = t & 31;
    const int row0 = blockIdx.x * BM;
    const int ar = t >> 2, ac = (t & 3) * 4;
    const int wrow = t >> 5, wcol = (t & 31) * 4;
    const float* Aa = &g_acc[(size_t)(row0 + ar) * HH];
    const float* Ax = &g_xp[(size_t)(row0 + ar) * HH];

    float4 pa = *(const float4*)(Aa + ac);
    STS_A(0);
    CP_W(0, Wl);

    float acc[8][4];
#pragma unroll
    for (int i = 0; i < 8; i++)
#pragma unroll
        for (int j = 0; j < 4; j++) acc[i][j] = 0.f;

    const int NT = 2 * HH / BK;  // 16
#pragma unroll
    for (int it = 0; it < NT; it++) {
        int cur = it & 1;
        CP_WAIT0();
        __syncthreads();
        if (it + 1 < NT) {
            int nx = it + 1;
            const float* Ap; const float* Wn;
            if (nx < 8) { Ap = Aa + nx * BK; Wn = Wl + (size_t)nx * BK * HH; }
            else        { Ap = Ax + (nx - 8) * BK; Wn = Wr + (size_t)(nx - 8) * BK * HH; }
            pa = *(const float4*)(Ap + ac);
            CP_W(cur ^ 1, Wn);
        }
        GEMM_COMPUTE(cur)
        if (it + 1 < NT) STS_A(cur ^ 1);
    }

    float b[4], lw[4], lb2[4];
#pragma unroll
    for (int j = 0; j < 4; j++) {
        b[j] = bl[tc * 4 + j]; lw[j] = lnw[tc * 4 + j]; lb2[j] = lnb[tc * 4 + j];
    }
#pragma unroll
    for (int i = 0; i < 8; i++) {
        float v[4]; float s = 0.f;
#pragma unroll
        for (int j = 0; j < 4; j++) { v[j] = acc[i][j] + b[j]; s += v[j]; }
        s = warp_sum(s);
        float mu = s * (1.f / HH);
        float q = 0.f;
#pragma unroll
        for (int j = 0; j < 4; j++) { v[j] -= mu; q += v[j] * v[j]; }
        q = warp_sum(q);
        float rstd = rsqrtf(q * (1.f / HH) + 1e-5f);
        float4 o;
        o.x = v[0] * rstd * lw[0] + lb2[0]; o.y = v[1] * rstd * lw[1] + lb2[1];
        o.z = v[2] * rstd * lw[2] + lb2[2]; o.w = v[3] * rstd * lw[3] + lb2[3];
        *(float4*)&g_h[(size_t)(row0 + tr * 8 + i) * HH + tc * 4] = o;
    }
}

// ---------------- edge MLP: gather-GEMM (K=256) + fused W2 reduction ----------------
__global__ void __launch_bounds__(NTH, 3) k_edgemlp(const int* __restrict__ eli, int Q,
        const float* __restrict__ W1, const float* __restrict__ b1,
        const float* __restrict__ W2, const float* __restrict__ b2,
        float* __restrict__ out) {
    __shared__ float As[2][BK][BM + 4];
    __shared__ float Ws[2][BK][BN];
    __shared__ int sbase[BM], dbase[BM];
    const int t = threadIdx.x;
    const int tr = t >> 5, tc = t & 31;
    const int q0 = blockIdx.x * BM;
    const int ar = t >> 2, ac = (t & 3) * 4;
    const int wrow = t >> 5, wcol = (t & 31) * 4;

    if (t < BM) {
        int q = q0 + t, s = 0, d = 0;
        if (q < Q) { s = eli[q]; d = eli[Q + q]; }
        sbase[t] = s * HH; dbase[t] = d * HH;
    }
    __syncthreads();
    const float* Asrc = &g_h[(size_t)sbase[ar]];
    const float* Adst = &g_h[(size_t)dbase[ar]];

    float4 pa = *(const float4*)(Asrc + ac);
    STS_A(0);
    CP_W(0, W1);

    float acc[8][4];
#pragma unroll
    for (int i = 0; i < 8; i++)
#pragma unroll
        for (int j = 0; j < 4; j++) acc[i][j] = 0.f;

    const int NT = 2 * HH / BK;  // 16
#pragma unroll
    for (int it = 0; it < NT; it++) {
        int cur = it & 1;
        CP_WAIT0();
        __syncthreads();
        if (it + 1 < NT) {
            int nx = it + 1;
            const float* Ap = (nx < 8) ? (Asrc + nx * BK) : (Adst + (nx - 8) * BK);
            pa = *(const float4*)(Ap + ac);
            CP_W(cur ^ 1, W1 + (size_t)nx * BK * HH);
        }
        GEMM_COMPUTE(cur)
        if (it + 1 < NT) STS_A(cur ^ 1);
    }

    float b[4], w2[4];
#pragma unroll
    for (int j = 0; j < 4; j++) { b[j] = b1[tc * 4 + j]; w2[j] = W2[tc * 4 + j]; }
    float b2v = b2[0];
#pragma unroll
    for (int i = 0; i < 8; i++) {
        float s = 0.f;
#pragma unroll
        for (int j = 0; j < 4; j++)
            s = fmaf(fmaxf(acc[i][j] + b[j], 0.f), w2[j], s);
        s = warp_sum(s);
        int q = q0 + tr * 8 + i;
        if (tc == 0 && q < Q) out[q] = s + b2v;
    }
}

// ---------------- host launch ----------------
extern "C" void kernel_launch(void* const* d_in, const int* in_sizes, int n_in,
                              void* d_out, int out_size) {
    const float* x    = (const float*)d_in[0];
    const int*   ei   = (const int*)d_in[1];
    const int*   eli  = (const int*)d_in[2];
    const float* p0Wp = (const float*)d_in[3];
    const float* p0bp = (const float*)d_in[4];
    const float* p0Wl = (const float*)d_in[5];
    const float* p0bl = (const float*)d_in[6];
    const float* p0Wr = (const float*)d_in[7];
    const float* Wp_s = (const float*)d_in[8];
    const float* bp_s = (const float*)d_in[9];
    const float* Wl_s = (const float*)d_in[10];
    const float* bl_s = (const float*)d_in[11];
    const float* Wr_s = (const float*)d_in[12];
    const float* ln_w = (const float*)d_in[13];
    const float* ln_b = (const float*)d_in[14];
    const float* eW1  = (const float*)d_in[15];
    const float* eb1  = (const float*)d_in[16];
    const float* eW2  = (const float*)d_in[17];
    const float* eb2  = (const float*)d_in[18];
    float* out = (float*)d_out;

    const int n = in_sizes[0] / 2;
    const int E = in_sizes[1] / 2;
    const int Q = in_sizes[2] / 2;

    // ---- CSR build (once; reused by all 3 aggregations) ----
    void* degp = nullptr;
    cudaGetSymbolAddress(&degp, g_deg);
    cudaMemsetAsync(degp, 0, (size_t)n * sizeof(int));
    k_hist<<<(E + 255) / 256, 256>>>(ei, E);
    const int nb = (n + SCAN_B - 1) / SCAN_B;
    k_scan1<<<nb, SCAN_B>>>(n);
    k_scan2<<<1, 1024>>>(nb);
    k_scan3<<<(n + 255) / 256, 256>>>(n, E);
    k_scatter<<<(E + 255) / 256, 256>>>(ei, E);

    // ---- layer 0 ----
    k_l0<<<(n + 255) / 256, 256>>>(x, p0Wp, p0bp, n);
    k_combine0<<<(n * 32 + 255) / 256, 256>>>(n, p0Wl, p0bl, p0Wr, ln_w, ln_b);

    // ---- layers 1..2 ----
    const int gb = (n + BM - 1) / BM;
    const int gaggB = (n * 32 + 255) / 256;
    for (int l = 0; l < 2; l++) {
        k_proj<<<gb, NTH>>>(Wp_s + (size_t)l * HH * HH, bp_s + (size_t)l * HH);
        k_gagg<<<gaggB, 256>>>(n);
        k_combine<<<gb, NTH>>>(Wl_s + (size_t)l * HH * HH, Wr_s + (size_t)l * HH * HH,
                               bl_s + (size_t)l * HH,
                               ln_w + (size_t)(l + 1) * HH, ln_b + (size_t)(l + 1) * HH);
    }
    k_edgemlp<<<(Q + BM - 1) / BM, NTH>>>(eli, Q, eW1, eb1, eW2, eb2, out);
}